// round 4
// baseline (speedup 1.0000x reference)
#include <cuda_runtime.h>

#define VS 100
#define BATCH 8
#define NUM_COORDS 65536
#define NPTS (BATCH * NUM_COORDS)          // 524288
#define NCELLS (BATCH * VS * VS * VS)      // 8,000,000

// Scratch: zero-initialized at module load; finalize re-zeroes exactly the
// occupied cells it consumes, so graph replays are deterministic with no
// explicit clear pass.
__device__ float g_sum[(size_t)NCELLS * 8];  // 256 MB; ch0..5 = sums
__device__ float g_cnt[NCELLS];              // 32 MB compact counts

__global__ void __launch_bounds__(256) scatter_kernel(
    const float* __restrict__ coords,
    const float* __restrict__ feats)
{
    int idx = blockIdx.x * blockDim.x + threadIdx.x;
    if (idx >= NPTS) return;

    float x = coords[idx * 3 + 0];
    float y = coords[idx * 3 + 1];
    float z = coords[idx * 3 + 2];

    // Reference constants collapse in f32: res = denom = 0.01f, shift = -0.01f
    int ix = (int)floorf((x + 0.01f) / 0.01f);
    int iy = (int)floorf((y + 0.01f) / 0.01f);
    int iz = (int)floorf((z + 0.01f) / 0.01f);

    // Indices outside [1,VS] land in the halo the reference slices away.
    if (ix < 1 || ix > VS || iy < 1 || iy > VS || iz < 1 || iz > VS) return;

    int b = idx >> 16;  // NUM_COORDS = 65536
    int cell = ((b * VS + (ix - 1)) * VS + (iy - 1)) * VS + (iz - 1);

    float f0 = feats[idx * 3 + 0];
    float f1 = feats[idx * 3 + 1];
    float f2 = feats[idx * 3 + 2];

    float* s = &g_sum[(size_t)cell * 8];
    // Vectorized return-less reductions (sm_90+): 3 atomic ops instead of 7.
    asm volatile("red.global.add.v4.f32 [%0], {%1, %2, %3, %4};"
                 :: "l"(s), "f"(x), "f"(y), "f"(z), "f"(f0) : "memory");
    asm volatile("red.global.add.v2.f32 [%0], {%1, %2};"
                 :: "l"(s + 4), "f"(f1), "f"(f2) : "memory");
    atomicAdd(&g_cnt[cell], 1.0f);
}

// Exact R2 finalize structure (known 118us): 1 cell/thread, default cache ops.
__global__ void __launch_bounds__(256) finalize_kernel(float* __restrict__ out)
{
    __shared__ float stage[256 * 10];  // 10 KB

    int cell = blockIdx.x * 256 + threadIdx.x;  // grid sized exactly to NCELLS

    // Decode cell -> (i, j, k) within the batch's 100^3 block.
    int k = cell % VS;
    int t = cell / VS;
    int j = t % VS;
    t /= VS;
    int i = t % VS;

    float cnt = g_cnt[cell];

    float v0 = 0.f, v1 = 0.f, v2 = 0.f, v3 = 0.f, v4 = 0.f, v5 = 0.f, occ = 0.f;
    if (cnt > 0.0f) {
        float4* sp = (float4*)&g_sum[(size_t)cell * 8];
        float4 a = sp[0];
        float4 b4 = sp[1];
        float r = 1.0f / cnt;  // one divide, six muls (<=1 ulp vs per-elem div)
        v0 = a.x * r;
        v1 = a.y * r;
        v2 = a.z * r;
        v3 = a.w * r;
        v4 = b4.x * r;
        v5 = b4.y * r;
        occ = 1.0f;
        // Self-clean scratch for the next graph replay.
        float4 z4 = make_float4(0.f, 0.f, 0.f, 0.f);
        sp[0] = z4;
        sp[1] = z4;
        g_cnt[cell] = 0.0f;
    }

    int base = threadIdx.x * 10;
    stage[base + 0] = v0;
    stage[base + 1] = v1;
    stage[base + 2] = v2;
    stage[base + 3] = v3;
    stage[base + 4] = v4;
    stage[base + 5] = v5;
    stage[base + 6] = (float)i * 0.01f;
    stage[base + 7] = (float)j * 0.01f;
    stage[base + 8] = (float)k * 0.01f;
    stage[base + 9] = occ;
    __syncthreads();

    // 256 cells * 10 f32 = 640 float4, fully coalesced.
    float4* o4 = (float4*)(out + (size_t)blockIdx.x * 2560);
    const float4* s4 = (const float4*)stage;
#pragma unroll
    for (int w = threadIdx.x; w < 640; w += 256) {
        o4[w] = s4[w];
    }
}

extern "C" void kernel_launch(void* const* d_in, const int* in_sizes, int n_in,
                              void* d_out, int out_size)
{
    const float* coords = (const float*)d_in[0];
    const float* feats  = (const float*)d_in[1];
    float* out = (float*)d_out;

    scatter_kernel<<<(NPTS + 255) / 256, 256>>>(coords, feats);
    finalize_kernel<<<NCELLS / 256, 256>>>(out);  // 31250 blocks
}

// round 5
// speedup vs baseline: 1.0473x; 1.0473x over previous
#include <cuda_runtime.h>

#define VS 100
#define BATCH 8
#define NUM_COORDS 65536
#define NPTS (BATCH * NUM_COORDS)          // 524288
#define NCELLS (BATCH * VS * VS * VS)      // 8,000,000

// Scratch: zero-initialized at module load; finalize re-zeroes exactly the
// occupied cells it consumes, so graph replays are deterministic with no
// explicit clear pass.
__device__ float g_sum[(size_t)NCELLS * 8];  // 256 MB; ch0..5 = sums
__device__ float g_cnt[NCELLS];              // 32 MB compact counts

__global__ void __launch_bounds__(256) scatter_kernel(
    const float* __restrict__ coords,
    const float* __restrict__ feats)
{
    int idx = blockIdx.x * blockDim.x + threadIdx.x;
    if (idx >= NPTS) return;

    float x = coords[idx * 3 + 0];
    float y = coords[idx * 3 + 1];
    float z = coords[idx * 3 + 2];

    // Reference constants collapse in f32: res = denom = 0.01f, shift = -0.01f
    int ix = (int)floorf((x + 0.01f) / 0.01f);
    int iy = (int)floorf((y + 0.01f) / 0.01f);
    int iz = (int)floorf((z + 0.01f) / 0.01f);

    // Indices outside [1,VS] land in the halo the reference slices away.
    if (ix < 1 || ix > VS || iy < 1 || iy > VS || iz < 1 || iz > VS) return;

    int b = idx >> 16;  // NUM_COORDS = 65536
    int cell = ((b * VS + (ix - 1)) * VS + (iy - 1)) * VS + (iz - 1);

    float f0 = feats[idx * 3 + 0];
    float f1 = feats[idx * 3 + 1];
    float f2 = feats[idx * 3 + 2];

    // Scalar return-less atomics -> native REDG (the validated fast path).
    float* s = &g_sum[(size_t)cell * 8];
    atomicAdd(s + 0, x);
    atomicAdd(s + 1, y);
    atomicAdd(s + 2, z);
    atomicAdd(s + 3, f0);
    atomicAdd(s + 4, f1);
    atomicAdd(s + 5, f2);
    atomicAdd(&g_cnt[cell], 1.0f);
}

// 2 cells per thread, default cache ops: 512 cells/block, 15625 blocks.
__global__ void __launch_bounds__(256) finalize_kernel(float* __restrict__ out)
{
    __shared__ float stage[512 * 10];  // 20 KB

    int base = blockIdx.x * 512;

    // Both count loads issued up front (MLP=2, independent scoreboards).
    float cnt0 = g_cnt[base + threadIdx.x];
    float cnt1 = g_cnt[base + threadIdx.x + 256];

#pragma unroll
    for (int q = 0; q < 2; q++) {
        int cl = threadIdx.x + q * 256;
        int cell = base + cl;
        float cnt = q ? cnt1 : cnt0;

        // Decode (i, j, k) within the batch's 100^3 block.
        int k = cell % VS;
        int t = cell / VS;
        int j = t % VS;
        int i = (t / VS) % VS;

        float v0 = 0.f, v1 = 0.f, v2 = 0.f, v3 = 0.f, v4 = 0.f, v5 = 0.f;
        float occ = 0.f;
        if (cnt > 0.0f) {
            float4* sp = (float4*)&g_sum[(size_t)cell * 8];
            float4 a  = sp[0];
            float4 b4 = sp[1];
            float r = 1.0f / cnt;  // one divide, six muls (<=1 ulp vs per-elem div)
            v0 = a.x * r;
            v1 = a.y * r;
            v2 = a.z * r;
            v3 = a.w * r;
            v4 = b4.x * r;
            v5 = b4.y * r;
            occ = 1.0f;
            // Self-clean scratch for the next graph replay.
            float4 z4 = make_float4(0.f, 0.f, 0.f, 0.f);
            sp[0] = z4;
            sp[1] = z4;
            g_cnt[cell] = 0.0f;
        }

        int sb = cl * 10;
        stage[sb + 0] = v0;
        stage[sb + 1] = v1;
        stage[sb + 2] = v2;
        stage[sb + 3] = v3;
        stage[sb + 4] = v4;
        stage[sb + 5] = v5;
        stage[sb + 6] = (float)i * 0.01f;
        stage[sb + 7] = (float)j * 0.01f;
        stage[sb + 8] = (float)k * 0.01f;
        stage[sb + 9] = occ;
    }
    __syncthreads();

    // 512 cells * 10 f32 = 1280 float4, fully coalesced.
    float4* o4 = (float4*)(out + (size_t)blockIdx.x * 5120);
    const float4* s4 = (const float4*)stage;
#pragma unroll
    for (int w = threadIdx.x; w < 1280; w += 256) {
        o4[w] = s4[w];
    }
}

extern "C" void kernel_launch(void* const* d_in, const int* in_sizes, int n_in,
                              void* d_out, int out_size)
{
    const float* coords = (const float*)d_in[0];
    const float* feats  = (const float*)d_in[1];
    float* out = (float*)d_out;

    scatter_kernel<<<(NPTS + 255) / 256, 256>>>(coords, feats);
    finalize_kernel<<<NCELLS / 512, 256>>>(out);  // 15625 blocks
}

// round 6
// speedup vs baseline: 3.0954x; 2.9557x over previous
#include <cuda_runtime.h>

#define VS 100
#define BATCH 8
#define NUM_COORDS 65536
#define NPTS (BATCH * NUM_COORDS)          // 524288
#define NCELLS (BATCH * VS * VS * VS)      // 8,000,000

// Scratch: zero-initialized at module load; every launch leaves it zeroed
// (finalize zeroes exactly the cells that were occupied), so graph replays
// are deterministic without an explicit clear pass.
__device__ float g_sum[(size_t)NCELLS * 8];  // 256 MB; ch0..5 = sums
__device__ float g_cnt[NCELLS];              // 32 MB compact counts

__global__ void __launch_bounds__(256) scatter_kernel(
    const float* __restrict__ coords,
    const float* __restrict__ feats)
{
    int idx = blockIdx.x * blockDim.x + threadIdx.x;
    if (idx >= NPTS) return;

    float x = coords[idx * 3 + 0];
    float y = coords[idx * 3 + 1];
    float z = coords[idx * 3 + 2];

    // Reference constants collapse in f32: res = denom = 0.01f, shift = -0.01f
    const float shift = 0.01f;
    const float denom = 0.01f;
    int ix = (int)floorf((x + shift) / denom);
    int iy = (int)floorf((y + shift) / denom);
    int iz = (int)floorf((z + shift) / denom);

    // Indices outside [1,VS] land in the halo the reference slices away.
    if (ix < 1 || ix > VS || iy < 1 || iy > VS || iz < 1 || iz > VS) return;

    int b = idx >> 16;  // NUM_COORDS = 65536
    int cell = ((b * VS + (ix - 1)) * VS + (iy - 1)) * VS + (iz - 1);

    float f0 = feats[idx * 3 + 0];
    float f1 = feats[idx * 3 + 1];
    float f2 = feats[idx * 3 + 2];

    float* s = &g_sum[(size_t)cell * 8];
    atomicAdd(s + 0, x);
    atomicAdd(s + 1, y);
    atomicAdd(s + 2, z);
    atomicAdd(s + 3, f0);
    atomicAdd(s + 4, f1);
    atomicAdd(s + 5, f2);
    atomicAdd(&g_cnt[cell], 1.0f);
}

__global__ void __launch_bounds__(256) finalize_kernel(float* __restrict__ out)
{
    __shared__ float stage[256 * 10];  // 10 KB

    int cell = blockIdx.x * 256 + threadIdx.x;  // grid sized exactly to NCELLS

    // Decode cell -> (i, j, k) within the batch's 100^3 block.
    int k = cell % VS;
    int t = cell / VS;
    int j = t % VS;
    t /= VS;
    int i = t % VS;

    float cnt = g_cnt[cell];

    float v0 = 0.f, v1 = 0.f, v2 = 0.f, v3 = 0.f, v4 = 0.f, v5 = 0.f, occ = 0.f;
    if (cnt > 0.0f) {
        float4* sp = (float4*)&g_sum[(size_t)cell * 8];
        float4 a = sp[0];
        float4 b4 = sp[1];
        v0 = a.x / cnt;
        v1 = a.y / cnt;
        v2 = a.z / cnt;
        v3 = a.w / cnt;
        v4 = b4.x / cnt;
        v5 = b4.y / cnt;
        occ = 1.0f;
        // Self-clean scratch for the next graph replay.
        float4 z4 = make_float4(0.f, 0.f, 0.f, 0.f);
        sp[0] = z4;
        sp[1] = z4;
        g_cnt[cell] = 0.0f;
    }

    int base = threadIdx.x * 10;
    stage[base + 0] = v0;
    stage[base + 1] = v1;
    stage[base + 2] = v2;
    stage[base + 3] = v3;
    stage[base + 4] = v4;
    stage[base + 5] = v5;
    stage[base + 6] = (float)i * 0.01f;
    stage[base + 7] = (float)j * 0.01f;
    stage[base + 8] = (float)k * 0.01f;
    stage[base + 9] = occ;
    __syncthreads();

    // 256 cells * 10 f32 = 640 float4, fully coalesced.
    float4* o4 = (float4*)(out + (size_t)blockIdx.x * 2560);
    const float4* s4 = (const float4*)stage;
#pragma unroll
    for (int w = threadIdx.x; w < 640; w += 256) {
        o4[w] = s4[w];
    }
}

extern "C" void kernel_launch(void* const* d_in, const int* in_sizes, int n_in,
                              void* d_out, int out_size)
{
    const float* coords = (const float*)d_in[0];
    const float* feats  = (const float*)d_in[1];
    float* out = (float*)d_out;

    scatter_kernel<<<(NPTS + 255) / 256, 256>>>(coords, feats);
    finalize_kernel<<<NCELLS / 256, 256>>>(out);  // 31250 blocks
}

// round 7
// speedup vs baseline: 3.3780x; 1.0913x over previous
#include <cuda_runtime.h>

#define VS 100
#define BATCH 8
#define NUM_COORDS 65536
#define NPTS (BATCH * NUM_COORDS)          // 524288
#define NCELLS (BATCH * VS * VS * VS)      // 8,000,000

// Scratch: zero-initialized at module load; finalize re-zeroes exactly the
// occupied cells it consumes, so graph replays are deterministic with no
// explicit clear pass.
__device__ float g_sum[(size_t)NCELLS * 8];  // 256 MB; ch0..5 = sums
__device__ float g_cnt[NCELLS];              // 32 MB compact counts

__global__ void __launch_bounds__(256) scatter_kernel(
    const float* __restrict__ coords,
    const float* __restrict__ feats)
{
    int idx = blockIdx.x * blockDim.x + threadIdx.x;
    if (idx >= NPTS) return;

    float x = coords[idx * 3 + 0];
    float y = coords[idx * 3 + 1];
    float z = coords[idx * 3 + 2];

    // Reference constants collapse in f32: res = denom = 0.01f, shift = -0.01f
    const float shift = 0.01f;
    const float denom = 0.01f;
    int ix = (int)floorf((x + shift) / denom);
    int iy = (int)floorf((y + shift) / denom);
    int iz = (int)floorf((z + shift) / denom);

    // Indices outside [1,VS] land in the halo the reference slices away.
    if (ix < 1 || ix > VS || iy < 1 || iy > VS || iz < 1 || iz > VS) return;

    int b = idx >> 16;  // NUM_COORDS = 65536
    int cell = ((b * VS + (ix - 1)) * VS + (iy - 1)) * VS + (iz - 1);

    float f0 = feats[idx * 3 + 0];
    float f1 = feats[idx * 3 + 1];
    float f2 = feats[idx * 3 + 2];

    float* s = &g_sum[(size_t)cell * 8];
    // Vectorized return-less reductions: 3 L2 atomic ops instead of 7.
    asm volatile("red.global.add.v4.f32 [%0], {%1, %2, %3, %4};"
                 :: "l"(s), "f"(x), "f"(y), "f"(z), "f"(f0) : "memory");
    asm volatile("red.global.add.v2.f32 [%0], {%1, %2};"
                 :: "l"(s + 4), "f"(f1), "f"(f2) : "memory");
    atomicAdd(&g_cnt[cell], 1.0f);
}

// Champion finalize (R2/R6 structure), untouched.
__global__ void __launch_bounds__(256) finalize_kernel(float* __restrict__ out)
{
    __shared__ float stage[256 * 10];  // 10 KB

    int cell = blockIdx.x * 256 + threadIdx.x;  // grid sized exactly to NCELLS

    // Decode cell -> (i, j, k) within the batch's 100^3 block.
    int k = cell % VS;
    int t = cell / VS;
    int j = t % VS;
    t /= VS;
    int i = t % VS;

    float cnt = g_cnt[cell];

    float v0 = 0.f, v1 = 0.f, v2 = 0.f, v3 = 0.f, v4 = 0.f, v5 = 0.f, occ = 0.f;
    if (cnt > 0.0f) {
        float4* sp = (float4*)&g_sum[(size_t)cell * 8];
        float4 a = sp[0];
        float4 b4 = sp[1];
        v0 = a.x / cnt;
        v1 = a.y / cnt;
        v2 = a.z / cnt;
        v3 = a.w / cnt;
        v4 = b4.x / cnt;
        v5 = b4.y / cnt;
        occ = 1.0f;
        // Self-clean scratch for the next graph replay.
        float4 z4 = make_float4(0.f, 0.f, 0.f, 0.f);
        sp[0] = z4;
        sp[1] = z4;
        g_cnt[cell] = 0.0f;
    }

    int base = threadIdx.x * 10;
    stage[base + 0] = v0;
    stage[base + 1] = v1;
    stage[base + 2] = v2;
    stage[base + 3] = v3;
    stage[base + 4] = v4;
    stage[base + 5] = v5;
    stage[base + 6] = (float)i * 0.01f;
    stage[base + 7] = (float)j * 0.01f;
    stage[base + 8] = (float)k * 0.01f;
    stage[base + 9] = occ;
    __syncthreads();

    // 256 cells * 10 f32 = 640 float4, fully coalesced.
    float4* o4 = (float4*)(out + (size_t)blockIdx.x * 2560);
    const float4* s4 = (const float4*)stage;
#pragma unroll
    for (int w = threadIdx.x; w < 640; w += 256) {
        o4[w] = s4[w];
    }
}

extern "C" void kernel_launch(void* const* d_in, const int* in_sizes, int n_in,
                              void* d_out, int out_size)
{
    const float* coords = (const float*)d_in[0];
    const float* feats  = (const float*)d_in[1];
    float* out = (float*)d_out;

    scatter_kernel<<<(NPTS + 255) / 256, 256>>>(coords, feats);
    finalize_kernel<<<NCELLS / 256, 256>>>(out);  // 31250 blocks
}

// round 8
// speedup vs baseline: 3.4467x; 1.0204x over previous
#include <cuda_runtime.h>
#include <cstdint>

#define VS 100
#define BATCH 8
#define NUM_COORDS 65536
#define NPTS (BATCH * NUM_COORDS)          // 524288
#define NCELLS (BATCH * VS * VS * VS)      // 8,000,000

// Scratch: zero-initialized at module load; finalize re-zeroes exactly the
// occupied cells it consumes, so graph replays are deterministic.
// g_sum ch0..5 = sums(x,y,z,f0,f1,f2), ch6 = count, ch7 = always 0.
__device__ float g_sum[(size_t)NCELLS * 8];  // 256 MB
__device__ float g_flag[NCELLS];             // 32 MB compact occupancy flags

__global__ void __launch_bounds__(256) scatter_kernel(
    const float* __restrict__ coords,
    const float* __restrict__ feats)
{
    int idx = blockIdx.x * blockDim.x + threadIdx.x;
    if (idx >= NPTS) return;

    float x = coords[idx * 3 + 0];
    float y = coords[idx * 3 + 1];
    float z = coords[idx * 3 + 2];

    // Reference constants collapse in f32: res = denom = 0.01f, shift = -0.01f
    const float shift = 0.01f;
    const float denom = 0.01f;
    int ix = (int)floorf((x + shift) / denom);
    int iy = (int)floorf((y + shift) / denom);
    int iz = (int)floorf((z + shift) / denom);

    // Halo guard (reference slices these away; with this data none occur).
    if (ix < 1 || ix > VS || iy < 1 || iy > VS || iz < 1 || iz > VS) return;

    int b = idx >> 16;  // NUM_COORDS = 65536
    int cell = ((b * VS + (ix - 1)) * VS + (iy - 1)) * VS + (iz - 1);

    float f0 = feats[idx * 3 + 0];
    float f1 = feats[idx * 3 + 1];
    float f2 = feats[idx * 3 + 2];

    float* s = &g_sum[(size_t)cell * 8];
    // Two v4 return-less reductions per point; count folded into ch6.
    asm volatile("red.global.add.v4.f32 [%0], {%1, %2, %3, %4};"
                 :: "l"(s), "f"(x), "f"(y), "f"(z), "f"(f0) : "memory");
    asm volatile("red.global.add.v4.f32 [%0], {%1, %2, %3, %4};"
                 :: "l"(s + 4), "f"(f1), "f"(f2), "f"(1.0f), "f"(0.0f) : "memory");
    // Benign-race occupancy flag (all writers store 1.0f).
    g_flag[cell] = 1.0f;
}

__global__ void __launch_bounds__(256) finalize_kernel(float* __restrict__ out)
{
    __shared__ __align__(16) float stage[256 * 10];  // 10 KB

    int cell = blockIdx.x * 256 + threadIdx.x;  // grid sized exactly to NCELLS

    // Decode cell -> (i, j, k) within the batch's 100^3 block.
    int k = cell % VS;
    int t = cell / VS;
    int j = t % VS;
    t /= VS;
    int i = t % VS;

    float flag = g_flag[cell];

    float v0 = 0.f, v1 = 0.f, v2 = 0.f, v3 = 0.f, v4 = 0.f, v5 = 0.f, occ = 0.f;
    if (flag > 0.0f) {
        float4* sp = (float4*)&g_sum[(size_t)cell * 8];
        float4 a = sp[0];
        float4 b4 = sp[1];
        float cnt = b4.z;  // count accumulated in ch6
        v0 = a.x / cnt;
        v1 = a.y / cnt;
        v2 = a.z / cnt;
        v3 = a.w / cnt;
        v4 = b4.x / cnt;
        v5 = b4.y / cnt;
        occ = 1.0f;
        // Self-clean scratch for the next graph replay.
        float4 z4 = make_float4(0.f, 0.f, 0.f, 0.f);
        sp[0] = z4;
        sp[1] = z4;
        g_flag[cell] = 0.0f;
    }

    int base = threadIdx.x * 10;
    stage[base + 0] = v0;
    stage[base + 1] = v1;
    stage[base + 2] = v2;
    stage[base + 3] = v3;
    stage[base + 4] = v4;
    stage[base + 5] = v5;
    stage[base + 6] = (float)i * 0.01f;
    stage[base + 7] = (float)j * 0.01f;
    stage[base + 8] = (float)k * 0.01f;
    stage[base + 9] = occ;
    __syncthreads();

    // One TMA bulk store: 10240 contiguous bytes smem -> gmem.
    if (threadIdx.x == 0) {
        uint32_t smem_addr = (uint32_t)__cvta_generic_to_shared(stage);
        float* dst = out + (size_t)blockIdx.x * 2560;
        asm volatile("fence.proxy.async.shared::cta;" ::: "memory");
        asm volatile("cp.async.bulk.global.shared::cta.bulk_group [%0], [%1], %2;"
                     :: "l"(dst), "r"(smem_addr), "r"(10240) : "memory");
        asm volatile("cp.async.bulk.commit_group;" ::: "memory");
        asm volatile("cp.async.bulk.wait_group 0;" ::: "memory");
    }
}

extern "C" void kernel_launch(void* const* d_in, const int* in_sizes, int n_in,
                              void* d_out, int out_size)
{
    const float* coords = (const float*)d_in[0];
    const float* feats  = (const float*)d_in[1];
    float* out = (float*)d_out;

    scatter_kernel<<<(NPTS + 255) / 256, 256>>>(coords, feats);
    finalize_kernel<<<NCELLS / 256, 256>>>(out);  // 31250 blocks
}

// round 9
// speedup vs baseline: 3.7833x; 1.0976x over previous
#include <cuda_runtime.h>
#include <cstdint>

#define VS 100
#define BATCH 8
#define NUM_COORDS 65536
#define NPTS (BATCH * NUM_COORDS)          // 524288
#define NCELLS (BATCH * VS * VS * VS)      // 8,000,000

#define GROUPS 5                            // cells per block = GROUPS*256 = 1280
#define CPB (GROUPS * 256)
#define NBLK (NCELLS / CPB)                 // 6250, exact

// Scratch: zero-initialized at module load; finalize re-zeroes exactly the
// occupied cells it consumes -> graph replays deterministic, no clear pass.
// g_sum ch0..5 = sums(x,y,z,f0,f1,f2), ch6 = count, ch7 = 0.
__device__ float g_sum[(size_t)NCELLS * 8];   // 256 MB
__device__ unsigned char g_flag[NCELLS];      // 8 MB occupancy flags

__global__ void __launch_bounds__(256) scatter_kernel(
    const float* __restrict__ coords,
    const float* __restrict__ feats)
{
    int idx = blockIdx.x * blockDim.x + threadIdx.x;
    if (idx >= NPTS) return;

    float x = coords[idx * 3 + 0];
    float y = coords[idx * 3 + 1];
    float z = coords[idx * 3 + 2];

    // Reference constants collapse in f32: res = denom = 0.01f, shift = -0.01f
    const float shift = 0.01f;
    const float denom = 0.01f;
    int ix = (int)floorf((x + shift) / denom);
    int iy = (int)floorf((y + shift) / denom);
    int iz = (int)floorf((z + shift) / denom);

    if (ix < 1 || ix > VS || iy < 1 || iy > VS || iz < 1 || iz > VS) return;

    int b = idx >> 16;  // NUM_COORDS = 65536
    int cell = ((b * VS + (ix - 1)) * VS + (iy - 1)) * VS + (iz - 1);

    float f0 = feats[idx * 3 + 0];
    float f1 = feats[idx * 3 + 1];
    float f2 = feats[idx * 3 + 2];

    float* s = &g_sum[(size_t)cell * 8];
    // Two v4 return-less reductions per point; count folded into ch6.
    asm volatile("red.global.add.v4.f32 [%0], {%1, %2, %3, %4};"
                 :: "l"(s), "f"(x), "f"(y), "f"(z), "f"(f0) : "memory");
    asm volatile("red.global.add.v4.f32 [%0], {%1, %2, %3, %4};"
                 :: "l"(s + 4), "f"(f1), "f"(f2), "f"(1.0f), "f"(0.0f) : "memory");
    // Benign-race occupancy flag (all writers store 1).
    g_flag[cell] = 1;
}

__global__ void __launch_bounds__(256) finalize_kernel(float* __restrict__ out)
{
    __shared__ __align__(16) float stage[2][2560];  // 2 x 10 KB double buffer

    int blockBase = blockIdx.x * CPB;

#pragma unroll
    for (int g = 0; g < GROUPS; g++) {
        int buf = g & 1;
        int cell = blockBase + g * 256 + threadIdx.x;

        // Decode (i, j, k) within the batch's 100^3 block.
        int k = cell % VS;
        int t = cell / VS;
        int j = t % VS;
        int i = (t / VS) % VS;

        unsigned char flag = g_flag[cell];

        float v0 = 0.f, v1 = 0.f, v2 = 0.f, v3 = 0.f, v4 = 0.f, v5 = 0.f;
        float occ = 0.f;
        if (flag) {
            float4* sp = (float4*)&g_sum[(size_t)cell * 8];
            float4 a = sp[0];
            float4 b4 = sp[1];
            float cnt = b4.z;  // count accumulated in ch6
            v0 = a.x / cnt;
            v1 = a.y / cnt;
            v2 = a.z / cnt;
            v3 = a.w / cnt;
            v4 = b4.x / cnt;
            v5 = b4.y / cnt;
            occ = 1.0f;
            // Self-clean scratch for the next graph replay.
            float4 z4 = make_float4(0.f, 0.f, 0.f, 0.f);
            sp[0] = z4;
            sp[1] = z4;
            g_flag[cell] = 0;
        }

        // Before overwriting this buffer, the bulk store issued on it two
        // groups ago must have drained (<=1 group outstanding).
        if (g >= 2) {
            if (threadIdx.x == 0) {
                asm volatile("cp.async.bulk.wait_group 1;" ::: "memory");
            }
            __syncthreads();
        }

        float* st = stage[buf] + threadIdx.x * 10;
        st[0] = v0;
        st[1] = v1;
        st[2] = v2;
        st[3] = v3;
        st[4] = v4;
        st[5] = v5;
        st[6] = (float)i * 0.01f;
        st[7] = (float)j * 0.01f;
        st[8] = (float)k * 0.01f;
        st[9] = occ;
        __syncthreads();

        if (threadIdx.x == 0) {
            uint32_t smem_addr = (uint32_t)__cvta_generic_to_shared(stage[buf]);
            float* dst = out + (size_t)blockBase * 10 + (size_t)g * 2560;
            asm volatile("fence.proxy.async.shared::cta;" ::: "memory");
            asm volatile("cp.async.bulk.global.shared::cta.bulk_group [%0], [%1], %2;"
                         :: "l"(dst), "r"(smem_addr), "r"(10240) : "memory");
            asm volatile("cp.async.bulk.commit_group;" ::: "memory");
        }
    }

    // Thread 0 keeps the CTA (and its smem) alive until all stores drain.
    if (threadIdx.x == 0) {
        asm volatile("cp.async.bulk.wait_group 0;" ::: "memory");
    }
}

extern "C" void kernel_launch(void* const* d_in, const int* in_sizes, int n_in,
                              void* d_out, int out_size)
{
    const float* coords = (const float*)d_in[0];
    const float* feats  = (const float*)d_in[1];
    float* out = (float*)d_out;

    scatter_kernel<<<(NPTS + 255) / 256, 256>>>(coords, feats);
    finalize_kernel<<<NBLK, 256>>>(out);  // 6250 blocks x 1280 cells
}